// round 3
// baseline (speedup 1.0000x reference)
#include <cuda_runtime.h>
#include <cuda_bf16.h>

#define N_NODES 100000
#define N_EDGES 1600000
#define IN_C 128
#define HID_C 256
#define OUT_C 128

// ---------------- scratch (static device globals; float4 => 16B aligned) ----------------
__device__ float4 g_agg1[N_NODES * IN_C / 4];    // x + sum x[src]         (51.2 MB)
__device__ float4 g_t   [N_NODES * HID_C / 4];   // mlp layer1 tmp         (102.4 MB)
__device__ float4 g_h   [N_NODES * HID_C / 4];   // output of conv1 (relu) (102.4 MB)
__device__ float4 g_agg2[N_NODES * HID_C / 4];   // h + sum h[src]         (102.4 MB)

// ---------------- vector float atomic reduction ----------------
__device__ __forceinline__ void red_add_v4(float4* p, float4 v) {
    asm volatile("red.global.add.v4.f32 [%0], {%1,%2,%3,%4};"
                 :: "l"(p), "f"(v.x), "f"(v.y), "f"(v.z), "f"(v.w)
                 : "memory");
}

// ---------------- edge scatter: one warp per edge ----------------
// agg[dst] += x[src], rows of V float4s (V = channels/4)
template <int V>
__global__ void __launch_bounds__(256) scatter_add_kernel(
    const float4* __restrict__ xin,
    const int* __restrict__ src,
    const int* __restrict__ dst,
    float4* __restrict__ agg)
{
    int gw = (int)((blockIdx.x * 256u + threadIdx.x) >> 5);
    if (gw >= N_EDGES) return;
    int lane = threadIdx.x & 31;
    int s = __ldg(&src[gw]);
    int d = __ldg(&dst[gw]);
#pragma unroll
    for (int i = 0; i < V / 32; i++) {
        float4 v = xin[(size_t)s * V + i * 32 + lane];
        red_add_v4(&agg[(size_t)d * V + i * 32 + lane], v);
    }
}

// ---------------- fp32 tiled GEMM + bias (+ optional ReLU) ----------------
// C[M, NTOT] = A[M, K] @ W[K, NTOT] + bias ; per-block tile 128x128, 256 thr, 8x8/thr
template <int K, int NTOT, bool RELU>
__global__ void __launch_bounds__(256, 2) gemm_bias_kernel(
    const float* __restrict__ A,
    const float* __restrict__ W,
    const float* __restrict__ bias,
    float* __restrict__ C,
    int M)
{
    constexpr int BM = 128, BN = 128, BK = 16;
    __shared__ float As[BK][BM];   // transposed: As[k][m]
    __shared__ float Ws[BK][BN];   // Ws[k][n]

    const int tid = threadIdx.x;
    const int m0 = blockIdx.x * BM;
    const int n0 = blockIdx.y * BN;
    const int tx = tid % 16;       // 16 col-groups of 8
    const int ty = tid / 16;       // 16 row-groups of 8

    float acc[8][8];
#pragma unroll
    for (int i = 0; i < 8; i++)
#pragma unroll
        for (int j = 0; j < 8; j++) acc[i][j] = 0.0f;

    const int ar = tid / 4;        // 0..63 (row within tile, two passes)
    const int ac4 = tid % 4;       // float4 index within BK=16
    const int wr = tid / 32;       // 0..7 (k within tile, two passes)
    const int wc4 = tid % 32;      // float4 col index within BN=128

    for (int k0 = 0; k0 < K; k0 += BK) {
        // A tile: 128 rows x 16 k -> As[k][m]
#pragma unroll
        for (int i = 0; i < 2; i++) {
            int row = ar + i * 64;
            float4 v = make_float4(0.f, 0.f, 0.f, 0.f);
            if (m0 + row < M)
                v = *(const float4*)&A[(size_t)(m0 + row) * K + k0 + ac4 * 4];
            As[ac4 * 4 + 0][row] = v.x;
            As[ac4 * 4 + 1][row] = v.y;
            As[ac4 * 4 + 2][row] = v.z;
            As[ac4 * 4 + 3][row] = v.w;
        }
        // W tile: 16 k x 128 n -> Ws[k][n]
#pragma unroll
        for (int i = 0; i < 2; i++) {
            int kk = wr + i * 8;
            *(float4*)&Ws[kk][wc4 * 4] =
                *(const float4*)&W[(size_t)(k0 + kk) * NTOT + n0 + wc4 * 4];
        }
        __syncthreads();

#pragma unroll
        for (int k = 0; k < BK; k++) {
            float a[8], w[8];
            *(float4*)&a[0] = *(const float4*)&As[k][ty * 8];
            *(float4*)&a[4] = *(const float4*)&As[k][ty * 8 + 4];
            *(float4*)&w[0] = *(const float4*)&Ws[k][tx * 8];
            *(float4*)&w[4] = *(const float4*)&Ws[k][tx * 8 + 4];
#pragma unroll
            for (int i = 0; i < 8; i++)
#pragma unroll
                for (int j = 0; j < 8; j++)
                    acc[i][j] = fmaf(a[i], w[j], acc[i][j]);
        }
        __syncthreads();
    }

    // epilogue: bias (+ relu), vectorized stores
    float bfr[8];
#pragma unroll
    for (int j = 0; j < 8; j++) bfr[j] = bias[n0 + tx * 8 + j];

#pragma unroll
    for (int i = 0; i < 8; i++) {
        int row = m0 + ty * 8 + i;
        if (row >= M) continue;
        float o[8];
#pragma unroll
        for (int j = 0; j < 8; j++) {
            float v = acc[i][j] + bfr[j];
            if (RELU) v = fmaxf(v, 0.0f);
            o[j] = v;
        }
        float* cp = &C[(size_t)row * NTOT + n0 + tx * 8];
        *(float4*)&cp[0] = *(float4*)&o[0];
        *(float4*)&cp[4] = *(float4*)&o[4];
    }
}

// ---------------- launch ----------------
extern "C" void kernel_launch(void* const* d_in, const int* in_sizes, int n_in,
                              void* d_out, int out_size)
{
    const float* x   = (const float*)d_in[0];
    const int*   ei  = (const int*)d_in[1];   // JAX x64 disabled: int64 request -> int32 array
    const float* W1a = (const float*)d_in[2];
    const float* b1a = (const float*)d_in[3];
    const float* W2a = (const float*)d_in[4];
    const float* b2a = (const float*)d_in[5];
    const float* W1b = (const float*)d_in[6];
    const float* b1b = (const float*)d_in[7];
    const float* W2b = (const float*)d_in[8];
    const float* b2b = (const float*)d_in[9];
    float* out = (float*)d_out;

    float4 *agg1, *t, *h, *agg2;
    cudaGetSymbolAddress((void**)&agg1, g_agg1);
    cudaGetSymbolAddress((void**)&t,    g_t);
    cudaGetSymbolAddress((void**)&h,    g_h);
    cudaGetSymbolAddress((void**)&agg2, g_agg2);

    const int* src = ei;            // edge_index[0]
    const int* dst = ei + N_EDGES;  // edge_index[1]

    const int scatterBlocks = (N_EDGES + 7) / 8;   // 8 warps (=8 edges) per block
    const int mBlocks = (N_NODES + 127) / 128;     // 782

    // conv1 aggregation: agg1 = x ; agg1[dst] += x[src]
    cudaMemcpyAsync(agg1, x, (size_t)N_NODES * IN_C * sizeof(float),
                    cudaMemcpyDeviceToDevice);
    scatter_add_kernel<IN_C / 4><<<scatterBlocks, 256>>>(
        (const float4*)x, src, dst, agg1);

    // conv1 MLP: t = relu(agg1 @ W1a + b1a) ; h = relu(t @ W2a + b2a)
    {
        dim3 grid(mBlocks, HID_C / 128);
        gemm_bias_kernel<IN_C, HID_C, true><<<grid, 256>>>(
            (const float*)agg1, W1a, b1a, (float*)t, N_NODES);
        gemm_bias_kernel<HID_C, HID_C, true><<<grid, 256>>>(
            (const float*)t, W2a, b2a, (float*)h, N_NODES);
    }

    // conv2 aggregation: agg2 = h ; agg2[dst] += h[src]
    cudaMemcpyAsync(agg2, h, (size_t)N_NODES * HID_C * sizeof(float),
                    cudaMemcpyDeviceToDevice);
    scatter_add_kernel<HID_C / 4><<<scatterBlocks, 256>>>(
        (const float4*)h, src, dst, agg2);

    // conv2 MLP: t = relu(agg2 @ W1b + b1b) ; out = t @ W2b + b2b
    {
        dim3 grid(mBlocks, HID_C / 128);
        gemm_bias_kernel<HID_C, HID_C, true><<<grid, 256>>>(
            (const float*)agg2, W1b, b1b, (float*)t, N_NODES);
    }
    {
        dim3 grid(mBlocks, OUT_C / 128);
        gemm_bias_kernel<HID_C, OUT_C, false><<<grid, 256>>>(
            (const float*)t, W2b, b2b, out, N_NODES);
    }
}

// round 5
// speedup vs baseline: 1.7797x; 1.7797x over previous
#include <cuda_runtime.h>
#include <cstdint>

#define N_NODES 100000
#define N_EDGES 1600000
#define IN_C 128
#define HID_C 256
#define OUT_C 128

// ================= scratch (static device globals; no allocation) =================
__device__ float4 g_agg1[N_NODES * IN_C / 4];    // x + sum x[src]
__device__ float4 g_t   [N_NODES * HID_C / 4];   // mlp layer1 tmp
__device__ float4 g_h   [N_NODES * HID_C / 4];   // conv1 output (relu)
__device__ float4 g_agg2[N_NODES * HID_C / 4];   // h + sum h[src]
__device__ float  g_Wt1[IN_C * HID_C];           // W1a^T  [N,K], tf32-rounded
__device__ float  g_Wt2[HID_C * HID_C];
__device__ float  g_Wt3[HID_C * HID_C];
__device__ float  g_Wt4[HID_C * OUT_C];

// ================= helpers =================
__device__ __forceinline__ uint32_t smem_u32(const void* p) {
    uint32_t a;
    asm("{ .reg .u64 t; cvta.to.shared.u64 t, %1; cvt.u32.u64 %0, t; }" : "=r"(a) : "l"(p));
    return a;
}
__device__ __forceinline__ float round_tf32(float x) {
    float r;
    asm("cvt.rna.tf32.f32 %0, %1;" : "=f"(r) : "f"(x));
    return r;
}
__device__ __forceinline__ void cp_async16(uint32_t dst, const void* src, bool pred) {
    int sz = pred ? 16 : 0;   // sz=0 -> zero-fill destination
    asm volatile("cp.async.ca.shared.global [%0], [%1], 16, %2;"
                 :: "r"(dst), "l"(src), "r"(sz) : "memory");
}
#define CP_COMMIT() asm volatile("cp.async.commit_group;" ::: "memory")
#define CP_WAIT(n)  asm volatile("cp.async.wait_group %0;" :: "n"(n) : "memory")

__device__ __forceinline__ void mma_tf32(float* d, uint32_t a0, uint32_t a1,
                                         uint32_t a2, uint32_t a3,
                                         uint32_t b0, uint32_t b1) {
    asm volatile(
        "mma.sync.aligned.m16n8k8.row.col.f32.tf32.tf32.f32 "
        "{%0,%1,%2,%3}, {%4,%5,%6,%7}, {%8,%9}, {%0,%1,%2,%3};"
        : "+f"(d[0]), "+f"(d[1]), "+f"(d[2]), "+f"(d[3])
        : "r"(a0), "r"(a1), "r"(a2), "r"(a3), "r"(b0), "r"(b1));
}

// ================= weight transpose + tf32 pre-round =================
__global__ void transpose_kernel(const float* __restrict__ W, float* __restrict__ Wt,
                                 int K, int N)
{
    int idx = blockIdx.x * 256 + threadIdx.x;
    if (idx >= K * N) return;
    int k = idx / N, n = idx % N;
    Wt[n * K + k] = round_tf32(W[idx]);
}

// ================= edge scatter: one warp per edge =================
__device__ __forceinline__ void red_add_v4(float4* p, float4 v) {
    asm volatile("red.global.add.v4.f32 [%0], {%1,%2,%3,%4};"
                 :: "l"(p), "f"(v.x), "f"(v.y), "f"(v.z), "f"(v.w) : "memory");
}

template <int V>
__global__ void __launch_bounds__(256) scatter_add_kernel(
    const float4* __restrict__ xin,
    const int* __restrict__ src,
    const int* __restrict__ dst,
    float4* __restrict__ agg)
{
    int gw = (int)((blockIdx.x * 256u + threadIdx.x) >> 5);
    if (gw >= N_EDGES) return;
    int lane = threadIdx.x & 31;
    int s = __ldg(&src[gw]);
    int d = __ldg(&dst[gw]);
#pragma unroll
    for (int i = 0; i < V / 32; i++) {
        float4 v = xin[(size_t)s * V + i * 32 + lane];
        red_add_v4(&agg[(size_t)d * V + i * 32 + lane], v);
    }
}

// ================= tf32 mma.sync GEMM =================
// C[M,N] = A[M,K] @ Wt[N,K]^T + bias ; CTA tile 128x128, 8 warps (4m x 2n),
// warp tile 32x64 = 2x8 m16n8k8 frags. cp.async double-buffered, BK=32.
template <int K, int N, bool RELU>
__global__ void __launch_bounds__(256) gemm_mma(
    const float* __restrict__ A,
    const float* __restrict__ Wt,     // [N, K] K-major, tf32-rounded
    const float* __restrict__ bias,
    float* __restrict__ C)
{
    constexpr int BM = 128, BN = 128, BK = 32, G = K / BK;
    constexpr int M = N_NODES;
    constexpr int PITCH = 36;                       // floats; conflict-free frag loads
    constexpr int ABUF = BM * PITCH;                // floats per A buffer
    constexpr int BBUF = BN * PITCH;

    extern __shared__ float sm[];                   // [2*ABUF + 2*BBUF]
    float* As = sm;
    float* Bs = sm + 2 * ABUF;
    const uint32_t sA = smem_u32(As);
    const uint32_t sB = smem_u32(Bs);

    const int tid  = threadIdx.x;
    const int wid  = tid >> 5;
    const int lane = tid & 31;
    const int gid  = lane >> 2;                     // 0..7
    const int tig  = lane & 3;                      // 0..3
    const int wm   = wid & 3;                       // 4 warps along M
    const int wn   = wid >> 2;                      // 2 warps along N
    const int rA   = wm * 32;
    const int rB   = wn * 64;
    const int m0   = blockIdx.x * BM;
    const int n0   = blockIdx.y * BN;

    float acc[2][8][4];
#pragma unroll
    for (int i = 0; i < 2; i++)
#pragma unroll
        for (int j = 0; j < 8; j++)
#pragma unroll
            for (int c = 0; c < 4; c++) acc[i][j][c] = 0.0f;

    // ---- cp.async chunk loader ----
    auto load_chunk = [&](int g) {
        const int s = g & 1;
#pragma unroll
        for (int j = 0; j < 4; j++) {               // A: 1024 x 16B
            int idx = j * 256 + tid;
            int row = idx >> 3, c4 = idx & 7;
            const float* gsrc = A + (size_t)(m0 + row) * K + g * BK + c4 * 4;
            uint32_t d = sA + (uint32_t)(s * ABUF + row * PITCH + c4 * 4) * 4u;
            cp_async16(d, gsrc, (m0 + row) < M);
        }
#pragma unroll
        for (int j = 0; j < 4; j++) {               // B: 1024 x 16B
            int idx = j * 256 + tid;
            int row = idx >> 3, c4 = idx & 7;
            const float* gsrc = Wt + (size_t)(n0 + row) * K + g * BK + c4 * 4;
            uint32_t d = sB + (uint32_t)(s * BBUF + row * PITCH + c4 * 4) * 4u;
            cp_async16(d, gsrc, true);
        }
        CP_COMMIT();
    };

    load_chunk(0);

    for (int g = 0; g < G; g++) {
        if (g + 1 < G) { load_chunk(g + 1); CP_WAIT(1); }
        else          { CP_WAIT(0); }
        __syncthreads();

        const float* as = As + (g & 1) * ABUF;
        const float* bs = Bs + (g & 1) * BBUF;

#pragma unroll
        for (int ks = 0; ks < 4; ks++) {
            const int k0 = ks * 8;
            uint32_t a[2][4];
#pragma unroll
            for (int mf = 0; mf < 2; mf++) {
                int base = rA + mf * 16;
                a[mf][0] = __float_as_uint(round_tf32(as[(base + gid)     * PITCH + k0 + tig]));
                a[mf][1] = __float_as_uint(round_tf32(as[(base + gid + 8) * PITCH + k0 + tig]));
                a[mf][2] = __float_as_uint(round_tf32(as[(base + gid)     * PITCH + k0 + tig + 4]));
                a[mf][3] = __float_as_uint(round_tf32(as[(base + gid + 8) * PITCH + k0 + tig + 4]));
            }
            uint32_t b[8][2];
#pragma unroll
            for (int nf = 0; nf < 8; nf++) {
                b[nf][0] = __float_as_uint(bs[(rB + nf * 8 + gid) * PITCH + k0 + tig]);
                b[nf][1] = __float_as_uint(bs[(rB + nf * 8 + gid) * PITCH + k0 + tig + 4]);
            }
#pragma unroll
            for (int mf = 0; mf < 2; mf++)
#pragma unroll
                for (int nf = 0; nf < 8; nf++)
                    mma_tf32(acc[mf][nf], a[mf][0], a[mf][1], a[mf][2], a[mf][3],
                             b[nf][0], b[nf][1]);
        }
        __syncthreads();
    }

    // ---- epilogue: bias (+relu), direct float2 stores from fragment layout ----
#pragma unroll
    for (int nf = 0; nf < 8; nf++) {
        int col = n0 + rB + nf * 8 + tig * 2;
        float b0 = bias[col], b1 = bias[col + 1];
#pragma unroll
        for (int mf = 0; mf < 2; mf++) {
            int r0 = m0 + rA + mf * 16 + gid;
            float v0 = acc[mf][nf][0] + b0, v1 = acc[mf][nf][1] + b1;
            float v2 = acc[mf][nf][2] + b0, v3 = acc[mf][nf][3] + b1;
            if (RELU) {
                v0 = fmaxf(v0, 0.f); v1 = fmaxf(v1, 0.f);
                v2 = fmaxf(v2, 0.f); v3 = fmaxf(v3, 0.f);
            }
            if (r0 < M)     *(float2*)&C[(size_t)r0 * N + col]       = make_float2(v0, v1);
            if (r0 + 8 < M) *(float2*)&C[(size_t)(r0 + 8) * N + col] = make_float2(v2, v3);
        }
    }
}

// ================= launch =================
extern "C" void kernel_launch(void* const* d_in, const int* in_sizes, int n_in,
                              void* d_out, int out_size)
{
    const float* x   = (const float*)d_in[0];
    const int*   ei  = (const int*)d_in[1];   // JAX x64 disabled: int32
    const float* W1a = (const float*)d_in[2];
    const float* b1a = (const float*)d_in[3];
    const float* W2a = (const float*)d_in[4];
    const float* b2a = (const float*)d_in[5];
    const float* W1b = (const float*)d_in[6];
    const float* b1b = (const float*)d_in[7];
    const float* W2b = (const float*)d_in[8];
    const float* b2b = (const float*)d_in[9];
    float* out = (float*)d_out;

    float4 *agg1, *t, *h, *agg2;
    float *Wt1, *Wt2, *Wt3, *Wt4;
    cudaGetSymbolAddress((void**)&agg1, g_agg1);
    cudaGetSymbolAddress((void**)&t,    g_t);
    cudaGetSymbolAddress((void**)&h,    g_h);
    cudaGetSymbolAddress((void**)&agg2, g_agg2);
    cudaGetSymbolAddress((void**)&Wt1,  g_Wt1);
    cudaGetSymbolAddress((void**)&Wt2,  g_Wt2);
    cudaGetSymbolAddress((void**)&Wt3,  g_Wt3);
    cudaGetSymbolAddress((void**)&Wt4,  g_Wt4);

    const int* src = ei;
    const int* dst = ei + N_EDGES;

    const int scatterBlocks = (N_EDGES + 7) / 8;
    const int mTiles = (N_NODES + 127) / 128;   // 782

    // dynamic smem: 2 x (128*36) floats for A + same for B = 73728 B
    const int SMEM = (2 * 128 * 36 + 2 * 128 * 36) * 4;
    cudaFuncSetAttribute(gemm_mma<IN_C,  HID_C, true >, cudaFuncAttributeMaxDynamicSharedMemorySize, SMEM);
    cudaFuncSetAttribute(gemm_mma<HID_C, HID_C, true >, cudaFuncAttributeMaxDynamicSharedMemorySize, SMEM);
    cudaFuncSetAttribute(gemm_mma<HID_C, OUT_C, false>, cudaFuncAttributeMaxDynamicSharedMemorySize, SMEM);

    // weight transposes + tf32 pre-round (tiny)
    transpose_kernel<<<(IN_C * HID_C + 255) / 256, 256>>>(W1a, Wt1, IN_C, HID_C);
    transpose_kernel<<<(HID_C * HID_C + 255) / 256, 256>>>(W2a, Wt2, HID_C, HID_C);
    transpose_kernel<<<(HID_C * HID_C + 255) / 256, 256>>>(W1b, Wt3, HID_C, HID_C);
    transpose_kernel<<<(HID_C * OUT_C + 255) / 256, 256>>>(W2b, Wt4, HID_C, OUT_C);

    // conv1 aggregation
    cudaMemcpyAsync(agg1, x, (size_t)N_NODES * IN_C * sizeof(float),
                    cudaMemcpyDeviceToDevice);
    scatter_add_kernel<IN_C / 4><<<scatterBlocks, 256>>>(
        (const float4*)x, src, dst, agg1);

    // conv1 MLP
    {
        dim3 grid(mTiles, HID_C / 128);
        gemm_mma<IN_C,  HID_C, true ><<<grid, 256, SMEM>>>(
            (const float*)agg1, Wt1, b1a, (float*)t);
        gemm_mma<HID_C, HID_C, true ><<<grid, 256, SMEM>>>(
            (const float*)t, Wt2, b2a, (float*)h);
    }

    // conv2 aggregation
    cudaMemcpyAsync(agg2, h, (size_t)N_NODES * HID_C * sizeof(float),
                    cudaMemcpyDeviceToDevice);
    scatter_add_kernel<HID_C / 4><<<scatterBlocks, 256>>>(
        (const float4*)h, src, dst, agg2);

    // conv2 MLP
    {
        dim3 grid(mTiles, HID_C / 128);
        gemm_mma<HID_C, HID_C, true ><<<grid, 256, SMEM>>>(
            (const float*)agg2, Wt3, b1b, (float*)t);
    }
    {
        dim3 grid(mTiles, OUT_C / 128);
        gemm_mma<HID_C, OUT_C, false><<<grid, 256, SMEM>>>(
            (const float*)t, Wt4, b2b, out);
    }
}

// round 6
// speedup vs baseline: 3.2835x; 1.8450x over previous
#include <cuda_runtime.h>
#include <cstdint>

#define N_NODES 100000
#define N_EDGES 1600000
#define IN_C 128
#define HID_C 256
#define OUT_C 128
#define SCAN_NB ((N_NODES + 1023) / 1024)   // 98

// ================= scratch (static device globals; no allocation) =================
__device__ float4 g_agg1[N_NODES * IN_C / 4];
__device__ float4 g_t   [N_NODES * HID_C / 4];
__device__ float4 g_h   [N_NODES * HID_C / 4];
__device__ float4 g_agg2[N_NODES * HID_C / 4];
__device__ float  g_Wt1[IN_C * HID_C];
__device__ float  g_Wt2[HID_C * HID_C];
__device__ float  g_Wt3[HID_C * HID_C];
__device__ float  g_Wt4[HID_C * OUT_C];
__device__ int    g_cnt[N_NODES];            // in-degree histogram
__device__ int    g_rowoff[N_NODES + 1];     // CSR row offsets (by dst)
__device__ int    g_cursor[N_NODES];         // fill cursors
__device__ int    g_csrsrc[N_EDGES];         // src ids, dst-sorted
__device__ int    g_bsum[SCAN_NB];           // scan block sums

// ================= helpers =================
__device__ __forceinline__ uint32_t smem_u32(const void* p) {
    uint32_t a;
    asm("{ .reg .u64 t; cvta.to.shared.u64 t, %1; cvt.u32.u64 %0, t; }" : "=r"(a) : "l"(p));
    return a;
}
__device__ __forceinline__ float round_tf32(float x) {
    float r;
    asm("cvt.rna.tf32.f32 %0, %1;" : "=f"(r) : "f"(x));
    return r;
}
__device__ __forceinline__ void cp_async16(uint32_t dst, const void* src, bool pred) {
    int sz = pred ? 16 : 0;
    asm volatile("cp.async.ca.shared.global [%0], [%1], 16, %2;"
                 :: "r"(dst), "l"(src), "r"(sz) : "memory");
}
#define CP_COMMIT() asm volatile("cp.async.commit_group;" ::: "memory")
#define CP_WAIT(n)  asm volatile("cp.async.wait_group %0;" :: "n"(n) : "memory")

__device__ __forceinline__ void mma_tf32(float* d, uint32_t a0, uint32_t a1,
                                         uint32_t a2, uint32_t a3,
                                         uint32_t b0, uint32_t b1) {
    asm volatile(
        "mma.sync.aligned.m16n8k8.row.col.f32.tf32.tf32.f32 "
        "{%0,%1,%2,%3}, {%4,%5,%6,%7}, {%8,%9}, {%0,%1,%2,%3};"
        : "+f"(d[0]), "+f"(d[1]), "+f"(d[2]), "+f"(d[3])
        : "r"(a0), "r"(a1), "r"(a2), "r"(a3), "r"(b0), "r"(b1));
}
__device__ __forceinline__ float4 f4add(float4 a, float4 b) {
    return make_float4(a.x + b.x, a.y + b.y, a.z + b.z, a.w + b.w);
}

// ================= weight transpose + tf32 pre-round =================
__global__ void transpose_kernel(const float* __restrict__ W, float* __restrict__ Wt,
                                 int K, int N)
{
    int idx = blockIdx.x * 256 + threadIdx.x;
    if (idx >= K * N) return;
    int k = idx / N, n = idx % N;
    Wt[n * K + k] = round_tf32(W[idx]);
}

// ================= CSR build =================
__global__ void hist_kernel(const int* __restrict__ dst, int* __restrict__ cnt)
{
    int e = blockIdx.x * 256 + threadIdx.x;
    if (e < N_EDGES) atomicAdd(&cnt[dst[e]], 1);
}

// exclusive scan, stage 1: per-1024 block scan
__global__ void scan1_kernel(const int* __restrict__ cnt, int* __restrict__ rowoff,
                             int* __restrict__ bsum)
{
    __shared__ int sh[1024];
    int tid = threadIdx.x;
    int i = blockIdx.x * 1024 + tid;
    int v = (i < N_NODES) ? cnt[i] : 0;
    sh[tid] = v;
    __syncthreads();
#pragma unroll
    for (int off = 1; off < 1024; off <<= 1) {
        int t = (tid >= off) ? sh[tid - off] : 0;
        __syncthreads();
        sh[tid] += t;
        __syncthreads();
    }
    if (i < N_NODES) rowoff[i] = sh[tid] - v;       // exclusive
    if (tid == 1023) bsum[blockIdx.x] = sh[tid];    // block total
}

// stage 2: single-block exclusive scan of block sums (SCAN_NB <= 128)
__global__ void scan2_kernel(int* __restrict__ bsum)
{
    __shared__ int sh[128];
    int tid = threadIdx.x;
    int v = (tid < SCAN_NB) ? bsum[tid] : 0;
    sh[tid] = v;
    __syncthreads();
#pragma unroll
    for (int off = 1; off < 128; off <<= 1) {
        int t = (tid >= off) ? sh[tid - off] : 0;
        __syncthreads();
        sh[tid] += t;
        __syncthreads();
    }
    if (tid < SCAN_NB) bsum[tid] = sh[tid] - v;     // exclusive
}

// stage 3: add block offsets; init cursors; set sentinel
__global__ void scan3_kernel(int* __restrict__ rowoff, const int* __restrict__ bsum,
                             int* __restrict__ cursor)
{
    int i = blockIdx.x * 1024 + threadIdx.x;
    if (i < N_NODES) {
        int r = rowoff[i] + bsum[blockIdx.x];
        rowoff[i] = r;
        cursor[i] = r;
    }
    if (i == 0) rowoff[N_NODES] = N_EDGES;
}

__global__ void fill_kernel(const int* __restrict__ src, const int* __restrict__ dst,
                            int* __restrict__ cursor, int* __restrict__ csrsrc)
{
    int e = blockIdx.x * 256 + threadIdx.x;
    if (e >= N_EDGES) return;
    int pos = atomicAdd(&cursor[dst[e]], 1);
    csrsrc[pos] = src[e];
}

// ================= CSR gather-reduce: agg[i] = x[i] + sum_{e in row i} x[csrsrc[e]] ====
// one warp per node; J = float4s per lane (1 for 128ch, 2 for 256ch)
template <int V>   // V = channels/4 (32 or 64)
__global__ void __launch_bounds__(256) csr_reduce_kernel(
    const float4* __restrict__ x,
    const int* __restrict__ rowoff,
    const int* __restrict__ csrsrc,
    float4* __restrict__ agg)
{
    constexpr int J = V / 32;
    int node = (int)((blockIdx.x * 256u + threadIdx.x) >> 5);
    if (node >= N_NODES) return;
    int lane = threadIdx.x & 31;

    float4 acc[J];
#pragma unroll
    for (int j = 0; j < J; j++)
        acc[j] = x[(size_t)node * V + j * 32 + lane];   // self term (fuses memcpy)

    int b = __ldg(&rowoff[node]);
    int e = __ldg(&rowoff[node + 1]);
    for (; b + 1 < e; b += 2) {
        int s0 = __ldg(&csrsrc[b]);
        int s1 = __ldg(&csrsrc[b + 1]);
#pragma unroll
        for (int j = 0; j < J; j++) {
            float4 v0 = x[(size_t)s0 * V + j * 32 + lane];
            float4 v1 = x[(size_t)s1 * V + j * 32 + lane];
            acc[j] = f4add(acc[j], f4add(v0, v1));
        }
    }
    if (b < e) {
        int s0 = __ldg(&csrsrc[b]);
#pragma unroll
        for (int j = 0; j < J; j++)
            acc[j] = f4add(acc[j], x[(size_t)s0 * V + j * 32 + lane]);
    }
#pragma unroll
    for (int j = 0; j < J; j++)
        agg[(size_t)node * V + j * 32 + lane] = acc[j];
}

// ================= tf32 mma.sync GEMM (unchanged from R5) =================
template <int K, int N, bool RELU>
__global__ void __launch_bounds__(256) gemm_mma(
    const float* __restrict__ A,
    const float* __restrict__ Wt,
    const float* __restrict__ bias,
    float* __restrict__ C)
{
    constexpr int BM = 128, BN = 128, BK = 32, G = K / BK;
    constexpr int M = N_NODES;
    constexpr int PITCH = 36;
    constexpr int ABUF = BM * PITCH;
    constexpr int BBUF = BN * PITCH;

    extern __shared__ float sm[];
    float* As = sm;
    float* Bs = sm + 2 * ABUF;
    const uint32_t sA = smem_u32(As);
    const uint32_t sB = smem_u32(Bs);

    const int tid  = threadIdx.x;
    const int wid  = tid >> 5;
    const int lane = tid & 31;
    const int gid  = lane >> 2;
    const int tig  = lane & 3;
    const int wm   = wid & 3;
    const int wn   = wid >> 2;
    const int rA   = wm * 32;
    const int rB   = wn * 64;
    const int m0   = blockIdx.x * BM;
    const int n0   = blockIdx.y * BN;

    float acc[2][8][4];
#pragma unroll
    for (int i = 0; i < 2; i++)
#pragma unroll
        for (int j = 0; j < 8; j++)
#pragma unroll
            for (int c = 0; c < 4; c++) acc[i][j][c] = 0.0f;

    auto load_chunk = [&](int g) {
        const int s = g & 1;
#pragma unroll
        for (int j = 0; j < 4; j++) {
            int idx = j * 256 + tid;
            int row = idx >> 3, c4 = idx & 7;
            const float* gsrc = A + (size_t)(m0 + row) * K + g * BK + c4 * 4;
            uint32_t d = sA + (uint32_t)(s * ABUF + row * PITCH + c4 * 4) * 4u;
            cp_async16(d, gsrc, (m0 + row) < M);
        }
#pragma unroll
        for (int j = 0; j < 4; j++) {
            int idx = j * 256 + tid;
            int row = idx >> 3, c4 = idx & 7;
            const float* gsrc = Wt + (size_t)(n0 + row) * K + g * BK + c4 * 4;
            uint32_t d = sB + (uint32_t)(s * BBUF + row * PITCH + c4 * 4) * 4u;
            cp_async16(d, gsrc, true);
        }
        CP_COMMIT();
    };

    load_chunk(0);

    for (int g = 0; g < G; g++) {
        if (g + 1 < G) { load_chunk(g + 1); CP_WAIT(1); }
        else          { CP_WAIT(0); }
        __syncthreads();

        const float* as = As + (g & 1) * ABUF;
        const float* bs = Bs + (g & 1) * BBUF;

#pragma unroll
        for (int ks = 0; ks < 4; ks++) {
            const int k0 = ks * 8;
            uint32_t a[2][4];
#pragma unroll
            for (int mf = 0; mf < 2; mf++) {
                int base = rA + mf * 16;
                a[mf][0] = __float_as_uint(round_tf32(as[(base + gid)     * PITCH + k0 + tig]));
                a[mf][1] = __float_as_uint(round_tf32(as[(base + gid + 8) * PITCH + k0 + tig]));
                a[mf][2] = __float_as_uint(round_tf32(as[(base + gid)     * PITCH + k0 + tig + 4]));
                a[mf][3] = __float_as_uint(round_tf32(as[(base + gid + 8) * PITCH + k0 + tig + 4]));
            }
            uint32_t b[8][2];
#pragma unroll
            for (int nf = 0; nf < 8; nf++) {
                b[nf][0] = __float_as_uint(bs[(rB + nf * 8 + gid) * PITCH + k0 + tig]);
                b[nf][1] = __float_as_uint(bs[(rB + nf * 8 + gid) * PITCH + k0 + tig + 4]);
            }
#pragma unroll
            for (int mf = 0; mf < 2; mf++)
#pragma unroll
                for (int nf = 0; nf < 8; nf++)
                    mma_tf32(acc[mf][nf], a[mf][0], a[mf][1], a[mf][2], a[mf][3],
                             b[nf][0], b[nf][1]);
        }
        __syncthreads();
    }

#pragma unroll
    for (int nf = 0; nf < 8; nf++) {
        int col = n0 + rB + nf * 8 + tig * 2;
        float b0 = bias[col], b1 = bias[col + 1];
#pragma unroll
        for (int mf = 0; mf < 2; mf++) {
            int r0 = m0 + rA + mf * 16 + gid;
            float v0 = acc[mf][nf][0] + b0, v1 = acc[mf][nf][1] + b1;
            float v2 = acc[mf][nf][2] + b0, v3 = acc[mf][nf][3] + b1;
            if (RELU) {
                v0 = fmaxf(v0, 0.f); v1 = fmaxf(v1, 0.f);
                v2 = fmaxf(v2, 0.f); v3 = fmaxf(v3, 0.f);
            }
            if (r0 < M)     *(float2*)&C[(size_t)r0 * N + col]       = make_float2(v0, v1);
            if (r0 + 8 < M) *(float2*)&C[(size_t)(r0 + 8) * N + col] = make_float2(v2, v3);
        }
    }
}

// ================= launch =================
extern "C" void kernel_launch(void* const* d_in, const int* in_sizes, int n_in,
                              void* d_out, int out_size)
{
    const float* x   = (const float*)d_in[0];
    const int*   ei  = (const int*)d_in[1];
    const float* W1a = (const float*)d_in[2];
    const float* b1a = (const float*)d_in[3];
    const float* W2a = (const float*)d_in[4];
    const float* b2a = (const float*)d_in[5];
    const float* W1b = (const float*)d_in[6];
    const float* b1b = (const float*)d_in[7];
    const float* W2b = (const float*)d_in[8];
    const float* b2b = (const float*)d_in[9];
    float* out = (float*)d_out;

    float4 *agg1, *t, *h, *agg2;
    float *Wt1, *Wt2, *Wt3, *Wt4;
    int *cnt, *rowoff, *cursor, *csrsrc, *bsum;
    cudaGetSymbolAddress((void**)&agg1, g_agg1);
    cudaGetSymbolAddress((void**)&t,    g_t);
    cudaGetSymbolAddress((void**)&h,    g_h);
    cudaGetSymbolAddress((void**)&agg2, g_agg2);
    cudaGetSymbolAddress((void**)&Wt1,  g_Wt1);
    cudaGetSymbolAddress((void**)&Wt2,  g_Wt2);
    cudaGetSymbolAddress((void**)&Wt3,  g_Wt3);
    cudaGetSymbolAddress((void**)&Wt4,  g_Wt4);
    cudaGetSymbolAddress((void**)&cnt,    g_cnt);
    cudaGetSymbolAddress((void**)&rowoff, g_rowoff);
    cudaGetSymbolAddress((void**)&cursor, g_cursor);
    cudaGetSymbolAddress((void**)&csrsrc, g_csrsrc);
    cudaGetSymbolAddress((void**)&bsum,   g_bsum);

    const int* src = ei;
    const int* dst = ei + N_EDGES;

    const int mTiles = (N_NODES + 127) / 128;
    const int eBlocks = (N_EDGES + 255) / 256;
    const int nWarpBlocks = (N_NODES * 32 + 255) / 256;

    const int SMEM = (2 * 128 * 36 + 2 * 128 * 36) * 4;
    cudaFuncSetAttribute(gemm_mma<IN_C,  HID_C, true >, cudaFuncAttributeMaxDynamicSharedMemorySize, SMEM);
    cudaFuncSetAttribute(gemm_mma<HID_C, HID_C, true >, cudaFuncAttributeMaxDynamicSharedMemorySize, SMEM);
    cudaFuncSetAttribute(gemm_mma<HID_C, OUT_C, false>, cudaFuncAttributeMaxDynamicSharedMemorySize, SMEM);

    // ---- CSR build (dst-sorted) ----
    cudaMemsetAsync(cnt, 0, N_NODES * sizeof(int));
    hist_kernel<<<eBlocks, 256>>>(dst, cnt);
    scan1_kernel<<<SCAN_NB, 1024>>>(cnt, rowoff, bsum);
    scan2_kernel<<<1, 128>>>(bsum);
    scan3_kernel<<<SCAN_NB, 1024>>>(rowoff, bsum, cursor);
    fill_kernel<<<eBlocks, 256>>>(src, dst, cursor, csrsrc);

    // ---- weight transposes + tf32 pre-round ----
    transpose_kernel<<<(IN_C * HID_C + 255) / 256, 256>>>(W1a, Wt1, IN_C, HID_C);
    transpose_kernel<<<(HID_C * HID_C + 255) / 256, 256>>>(W2a, Wt2, HID_C, HID_C);
    transpose_kernel<<<(HID_C * HID_C + 255) / 256, 256>>>(W1b, Wt3, HID_C, HID_C);
    transpose_kernel<<<(HID_C * OUT_C + 255) / 256, 256>>>(W2b, Wt4, HID_C, OUT_C);

    // ---- conv1: agg1 = x + gather-sum(x) ; MLP ----
    csr_reduce_kernel<IN_C / 4><<<nWarpBlocks, 256>>>(
        (const float4*)x, rowoff, csrsrc, agg1);
    {
        dim3 grid(mTiles, HID_C / 128);
        gemm_mma<IN_C,  HID_C, true ><<<grid, 256, SMEM>>>(
            (const float*)agg1, Wt1, b1a, (float*)t);
        gemm_mma<HID_C, HID_C, true ><<<grid, 256, SMEM>>>(
            (const float*)t, Wt2, b2a, (float*)h);
    }

    // ---- conv2: agg2 = h + gather-sum(h) ; MLP ----
    csr_reduce_kernel<HID_C / 4><<<nWarpBlocks, 256>>>(
        (const float4*)h, rowoff, csrsrc, agg2);
    {
        dim3 grid(mTiles, HID_C / 128);
        gemm_mma<HID_C, HID_C, true ><<<grid, 256, SMEM>>>(
            (const float*)agg2, Wt3, b1b, (float*)t);
    }
    {
        dim3 grid(mTiles, OUT_C / 128);
        gemm_mma<HID_C, OUT_C, false><<<grid, 256, SMEM>>>(
            (const float*)t, Wt4, b2b, out);
    }
}

// round 7
// speedup vs baseline: 3.3179x; 1.0105x over previous
#include <cuda_runtime.h>
#include <cstdint>

#define N_NODES 100000
#define N_EDGES 1600000
#define IN_C 128
#define HID_C 256
#define OUT_C 128
#define SCAN_NB ((N_NODES + 1023) / 1024)   // 98

// ================= scratch (static device globals; no allocation) =================
__device__ float4 g_agg1[N_NODES * IN_C / 4];
__device__ float4 g_t   [N_NODES * HID_C / 4];
__device__ float4 g_h   [N_NODES * HID_C / 4];
__device__ float4 g_agg2[N_NODES * HID_C / 4];
__device__ float  g_Wf1[IN_C * HID_C];       // fragment-packed weights
__device__ float  g_Wf2[HID_C * HID_C];
__device__ float  g_Wf3[HID_C * HID_C];
__device__ float  g_Wf4[HID_C * OUT_C];
__device__ int    g_cnt[N_NODES];
__device__ int    g_rowoff[N_NODES + 1];
__device__ int    g_cursor[N_NODES];
__device__ int    g_csrsrc[N_EDGES];
__device__ int    g_bsum[SCAN_NB];

// ================= helpers =================
__device__ __forceinline__ uint32_t smem_u32(const void* p) {
    uint32_t a;
    asm("{ .reg .u64 t; cvta.to.shared.u64 t, %1; cvt.u32.u64 %0, t; }" : "=r"(a) : "l"(p));
    return a;
}
__device__ __forceinline__ float round_tf32(float x) {
    float r;
    asm("cvt.rna.tf32.f32 %0, %1;" : "=f"(r) : "f"(x));
    return r;
}
__device__ __forceinline__ void cp_async16(uint32_t dst, const void* src, bool pred) {
    int sz = pred ? 16 : 0;
    asm volatile("cp.async.ca.shared.global [%0], [%1], 16, %2;"
                 :: "r"(dst), "l"(src), "r"(sz) : "memory");
}
#define CP_COMMIT() asm volatile("cp.async.commit_group;" ::: "memory")
#define CP_WAIT(n)  asm volatile("cp.async.wait_group %0;" :: "n"(n) : "memory")

__device__ __forceinline__ void mma_tf32(float* d, uint32_t a0, uint32_t a1,
                                         uint32_t a2, uint32_t a3,
                                         uint32_t b0, uint32_t b1) {
    asm volatile(
        "mma.sync.aligned.m16n8k8.row.col.f32.tf32.tf32.f32 "
        "{%0,%1,%2,%3}, {%4,%5,%6,%7}, {%8,%9}, {%0,%1,%2,%3};"
        : "+f"(d[0]), "+f"(d[1]), "+f"(d[2]), "+f"(d[3])
        : "r"(a0), "r"(a1), "r"(a2), "r"(a3), "r"(b0), "r"(b1));
}
__device__ __forceinline__ float4 f4add(float4 a, float4 b) {
    return make_float4(a.x + b.x, a.y + b.y, a.z + b.z, a.w + b.w);
}

// ================= weight fragment-pack (replaces transpose) =================
// Layout: [ntile][g][ks][wn][pair][lane] -> float4 {b(2p,k0),b(2p,k0+4),b(2p+1,k0),b(2p+1,k0+4)}
// n = nt*128 + wn*64 + (2p + jn)*8 + lane/4 ; k = g*32 + ks*8 + lane%4 (+4 for second reg)
template <int K, int NTOT>
__global__ void pack_kernel(const float* __restrict__ W, float* __restrict__ Wf)
{
    constexpr int G = K / 32;
    int id = blockIdx.x * 256 + threadIdx.x;          // one float4 per thread
    if (id >= K * NTOT / 4) return;
    int lane = id & 31;
    int p    = (id >> 5) & 3;
    int wn   = (id >> 7) & 1;
    int ks   = (id >> 8) & 3;
    int g    = (id >> 10) % G;
    int nt   = id / (1024 * G);

    int nbase = nt * 128 + wn * 64 + (lane >> 2);
    int kbase = g * 32 + ks * 8 + (lane & 3);
    float4 v;
    v.x = round_tf32(W[(size_t)(kbase)     * NTOT + nbase + (2 * p)     * 8]);
    v.y = round_tf32(W[(size_t)(kbase + 4) * NTOT + nbase + (2 * p)     * 8]);
    v.z = round_tf32(W[(size_t)(kbase)     * NTOT + nbase + (2 * p + 1) * 8]);
    v.w = round_tf32(W[(size_t)(kbase + 4) * NTOT + nbase + (2 * p + 1) * 8]);
    *(float4*)&Wf[(size_t)id * 4] = v;
}

// ================= CSR build =================
__global__ void hist_kernel(const int* __restrict__ dst, int* __restrict__ cnt)
{
    int e = blockIdx.x * 256 + threadIdx.x;
    if (e < N_EDGES) atomicAdd(&cnt[dst[e]], 1);
}

__global__ void scan1_kernel(const int* __restrict__ cnt, int* __restrict__ rowoff,
                             int* __restrict__ bsum)
{
    __shared__ int sh[1024];
    int tid = threadIdx.x;
    int i = blockIdx.x * 1024 + tid;
    int v = (i < N_NODES) ? cnt[i] : 0;
    sh[tid] = v;
    __syncthreads();
#pragma unroll
    for (int off = 1; off < 1024; off <<= 1) {
        int t = (tid >= off) ? sh[tid - off] : 0;
        __syncthreads();
        sh[tid] += t;
        __syncthreads();
    }
    if (i < N_NODES) rowoff[i] = sh[tid] - v;
    if (tid == 1023) bsum[blockIdx.x] = sh[tid];
}

__global__ void scan2_kernel(int* __restrict__ bsum)
{
    __shared__ int sh[128];
    int tid = threadIdx.x;
    int v = (tid < SCAN_NB) ? bsum[tid] : 0;
    sh[tid] = v;
    __syncthreads();
#pragma unroll
    for (int off = 1; off < 128; off <<= 1) {
        int t = (tid >= off) ? sh[tid - off] : 0;
        __syncthreads();
        sh[tid] += t;
        __syncthreads();
    }
    if (tid < SCAN_NB) bsum[tid] = sh[tid] - v;
}

__global__ void scan3_kernel(int* __restrict__ rowoff, const int* __restrict__ bsum,
                             int* __restrict__ cursor)
{
    int i = blockIdx.x * 1024 + threadIdx.x;
    if (i < N_NODES) {
        int r = rowoff[i] + bsum[blockIdx.x];
        rowoff[i] = r;
        cursor[i] = r;
    }
    if (i == 0) rowoff[N_NODES] = N_EDGES;
}

__global__ void fill_kernel(const int* __restrict__ src, const int* __restrict__ dst,
                            int* __restrict__ cursor, int* __restrict__ csrsrc)
{
    int e = blockIdx.x * 256 + threadIdx.x;
    if (e >= N_EDGES) return;
    int pos = atomicAdd(&cursor[dst[e]], 1);
    csrsrc[pos] = src[e];
}

// ================= CSR gather-reduce =================
template <int V>   // V = channels/4
__global__ void __launch_bounds__(256) csr_reduce_kernel(
    const float4* __restrict__ x,
    const int* __restrict__ rowoff,
    const int* __restrict__ csrsrc,
    float4* __restrict__ agg)
{
    constexpr int J = V / 32;
    int node = (int)((blockIdx.x * 256u + threadIdx.x) >> 5);
    if (node >= N_NODES) return;
    int lane = threadIdx.x & 31;

    float4 acc[J];
#pragma unroll
    for (int j = 0; j < J; j++)
        acc[j] = x[(size_t)node * V + j * 32 + lane];

    int b = __ldg(&rowoff[node]);
    int e = __ldg(&rowoff[node + 1]);
    for (; b + 1 < e; b += 2) {
        int s0 = __ldg(&csrsrc[b]);
        int s1 = __ldg(&csrsrc[b + 1]);
#pragma unroll
        for (int j = 0; j < J; j++) {
            float4 v0 = x[(size_t)s0 * V + j * 32 + lane];
            float4 v1 = x[(size_t)s1 * V + j * 32 + lane];
            acc[j] = f4add(acc[j], f4add(v0, v1));
        }
    }
    if (b < e) {
        int s0 = __ldg(&csrsrc[b]);
#pragma unroll
        for (int j = 0; j < J; j++)
            acc[j] = f4add(acc[j], x[(size_t)s0 * V + j * 32 + lane]);
    }
#pragma unroll
    for (int j = 0; j < J; j++)
        agg[(size_t)node * V + j * 32 + lane] = acc[j];
}

// ================= tf32 mma.sync GEMM, fragment-packed B =================
template <int K, int N, bool RELU>
__global__ void __launch_bounds__(256) gemm_mma(
    const float* __restrict__ A,
    const float* __restrict__ Wf,     // fragment-packed, tf32-rounded
    const float* __restrict__ bias,
    float* __restrict__ C)
{
    constexpr int BM = 128, BK = 32, G = K / BK;
    constexpr int M = N_NODES;
    constexpr int PITCH = 36;
    constexpr int ABUF = BM * PITCH;                // floats
    constexpr int BBUF = 4096;                      // floats: packed 128x32 chunk

    extern __shared__ float sm[];
    float* As = sm;
    float* Bs = sm + 2 * ABUF;
    const uint32_t sA = smem_u32(As);
    const uint32_t sB = smem_u32(Bs);

    const int tid  = threadIdx.x;
    const int wid  = tid >> 5;
    const int lane = tid & 31;
    const int gid  = lane >> 2;
    const int tig  = lane & 3;
    const int wm   = wid & 3;
    const int wn   = wid >> 2;
    const int rA   = wm * 32;
    const int rB   = wn * 64;
    const int m0   = blockIdx.x * BM;
    const int n0   = blockIdx.y * 128;

    float acc[2][8][4];
#pragma unroll
    for (int i = 0; i < 2; i++)
#pragma unroll
        for (int j = 0; j < 8; j++)
#pragma unroll
            for (int c = 0; c < 4; c++) acc[i][j][c] = 0.0f;

    const float* Wchunk = Wf + (size_t)blockIdx.y * G * BBUF;

    auto load_chunk = [&](int g) {
        const int s = g & 1;
#pragma unroll
        for (int j = 0; j < 4; j++) {               // A: 1024 x 16B
            int idx = j * 256 + tid;
            int row = idx >> 3, c4 = idx & 7;
            const float* gsrc = A + (size_t)(m0 + row) * K + g * BK + c4 * 4;
            uint32_t d = sA + (uint32_t)(s * ABUF + row * PITCH + c4 * 4) * 4u;
            cp_async16(d, gsrc, (m0 + row) < M);
        }
        const float* Bg = Wchunk + (size_t)g * BBUF;
#pragma unroll
        for (int j = 0; j < 4; j++) {               // B: 1024 x 16B contiguous
            int idx = j * 256 + tid;
            uint32_t d = sB + (uint32_t)(s * BBUF + idx * 4) * 4u;
            cp_async16(d, Bg + idx * 4, true);
        }
        CP_COMMIT();
    };

    load_chunk(0);

    for (int g = 0; g < G; g++) {
        if (g + 1 < G) { load_chunk(g + 1); CP_WAIT(1); }
        else          { CP_WAIT(0); }
        __syncthreads();

        const float* as = As + (g & 1) * ABUF;
        const float* bs = Bs + (g & 1) * BBUF;

#pragma unroll
        for (int ks = 0; ks < 4; ks++) {
            const int k0 = ks * 8;
            uint32_t a[2][4];
#pragma unroll
            for (int mf = 0; mf < 2; mf++) {
                int base = rA + mf * 16;
                a[mf][0] = __float_as_uint(round_tf32(as[(base + gid)     * PITCH + k0 + tig]));
                a[mf][1] = __float_as_uint(round_tf32(as[(base + gid + 8) * PITCH + k0 + tig]));
                a[mf][2] = __float_as_uint(round_tf32(as[(base + gid)     * PITCH + k0 + tig + 4]));
                a[mf][3] = __float_as_uint(round_tf32(as[(base + gid + 8) * PITCH + k0 + tig + 4]));
            }
            // B fragments: 4 conflict-free LDS.128 from packed layout
            uint32_t b[8][2];
#pragma unroll
            for (int p = 0; p < 4; p++) {
                float4 q = *(const float4*)&bs[(((ks * 2 + wn) * 4 + p) * 32 + lane) * 4];
                b[2 * p][0]     = __float_as_uint(q.x);
                b[2 * p][1]     = __float_as_uint(q.y);
                b[2 * p + 1][0] = __float_as_uint(q.z);
                b[2 * p + 1][1] = __float_as_uint(q.w);
            }
#pragma unroll
            for (int mf = 0; mf < 2; mf++)
#pragma unroll
                for (int nf = 0; nf < 8; nf++)
                    mma_tf32(acc[mf][nf], a[mf][0], a[mf][1], a[mf][2], a[mf][3],
                             b[nf][0], b[nf][1]);
        }
        __syncthreads();
    }

#pragma unroll
    for (int nf = 0; nf < 8; nf++) {
        int col = n0 + rB + nf * 8 + tig * 2;
        float b0 = bias[col], b1 = bias[col + 1];
#pragma unroll
        for (int mf = 0; mf < 2; mf++) {
            int r0 = m0 + rA + mf * 16 + gid;
            float v0 = acc[mf][nf][0] + b0, v1 = acc[mf][nf][1] + b1;
            float v2 = acc[mf][nf][2] + b0, v3 = acc[mf][nf][3] + b1;
            if (RELU) {
                v0 = fmaxf(v0, 0.f); v1 = fmaxf(v1, 0.f);
                v2 = fmaxf(v2, 0.f); v3 = fmaxf(v3, 0.f);
            }
            if (r0 < M)     *(float2*)&C[(size_t)r0 * N + col]       = make_float2(v0, v1);
            if (r0 + 8 < M) *(float2*)&C[(size_t)(r0 + 8) * N + col] = make_float2(v2, v3);
        }
    }
}

// ================= launch =================
extern "C" void kernel_launch(void* const* d_in, const int* in_sizes, int n_in,
                              void* d_out, int out_size)
{
    const float* x   = (const float*)d_in[0];
    const int*   ei  = (const int*)d_in[1];
    const float* W1a = (const float*)d_in[2];
    const float* b1a = (const float*)d_in[3];
    const float* W2a = (const float*)d_in[4];
    const float* b2a = (const float*)d_in[5];
    const float* W1b = (const float*)d_in[6];
    const float* b1b = (const float*)d_in[7];
    const float* W2b = (const float*)d_in[8];
    const float* b2b = (const float*)d_in[9];
    float* out = (float*)d_out;

    float4 *agg1, *t, *h, *agg2;
    float *Wf1, *Wf2, *Wf3, *Wf4;
    int *cnt, *rowoff, *cursor, *csrsrc, *bsum;
    cudaGetSymbolAddress((void**)&agg1, g_agg1);
    cudaGetSymbolAddress((void**)&t,    g_t);
    cudaGetSymbolAddress((void**)&h,    g_h);
    cudaGetSymbolAddress((void**)&agg2, g_agg2);
    cudaGetSymbolAddress((void**)&Wf1,  g_Wf1);
    cudaGetSymbolAddress((void**)&Wf2,  g_Wf2);
    cudaGetSymbolAddress((void**)&Wf3,  g_Wf3);
    cudaGetSymbolAddress((void**)&Wf4,  g_Wf4);
    cudaGetSymbolAddress((void**)&cnt,    g_cnt);
    cudaGetSymbolAddress((void**)&rowoff, g_rowoff);
    cudaGetSymbolAddress((void**)&cursor, g_cursor);
    cudaGetSymbolAddress((void**)&csrsrc, g_csrsrc);
    cudaGetSymbolAddress((void**)&bsum,   g_bsum);

    const int* src = ei;
    const int* dst = ei + N_EDGES;

    const int mTiles = (N_NODES + 127) / 128;
    const int eBlocks = (N_EDGES + 255) / 256;
    const int nWarpBlocks = (N_NODES * 32 + 255) / 256;

    const int SMEM = (2 * 128 * 36 + 2 * 4096) * 4;  // 69632 B
    cudaFuncSetAttribute(gemm_mma<IN_C,  HID_C, true >, cudaFuncAttributeMaxDynamicSharedMemorySize, SMEM);
    cudaFuncSetAttribute(gemm_mma<HID_C, HID_C, true >, cudaFuncAttributeMaxDynamicSharedMemorySize, SMEM);
    cudaFuncSetAttribute(gemm_mma<HID_C, OUT_C, false>, cudaFuncAttributeMaxDynamicSharedMemorySize, SMEM);

    // ---- CSR build (dst-sorted) ----
    cudaMemsetAsync(cnt, 0, N_NODES * sizeof(int));
    hist_kernel<<<eBlocks, 256>>>(dst, cnt);
    scan1_kernel<<<SCAN_NB, 1024>>>(cnt, rowoff, bsum);
    scan2_kernel<<<1, 128>>>(bsum);
    scan3_kernel<<<SCAN_NB, 1024>>>(rowoff, bsum, cursor);
    fill_kernel<<<eBlocks, 256>>>(src, dst, cursor, csrsrc);

    // ---- weight fragment packs (tiny) ----
    pack_kernel<IN_C,  HID_C><<<(IN_C * HID_C / 4 + 255) / 256, 256>>>(W1a, Wf1);
    pack_kernel<HID_C, HID_C><<<(HID_C * HID_C / 4 + 255) / 256, 256>>>(W2a, Wf2);
    pack_kernel<HID_C, HID_C><<<(HID_C * HID_C / 4 + 255) / 256, 256>>>(W1b, Wf3);
    pack_kernel<HID_C, OUT_C><<<(HID_C * OUT_C / 4 + 255) / 256, 256>>>(W2b, Wf4);

    // ---- conv1 ----
    csr_reduce_kernel<IN_C / 4><<<nWarpBlocks, 256>>>(
        (const float4*)x, rowoff, csrsrc, agg1);
    {
        dim3 grid(mTiles, HID_C / 128);
        gemm_mma<IN_C,  HID_C, true ><<<grid, 256, SMEM>>>(
            (const float*)agg1, Wf1, b1a, (float*)t);
        gemm_mma<HID_C, HID_C, true ><<<grid, 256, SMEM>>>(
            (const float*)t, Wf2, b2a, (float*)h);
    }

    // ---- conv2 ----
    csr_reduce_kernel<HID_C / 4><<<nWarpBlocks, 256>>>(
        (const float4*)h, rowoff, csrsrc, agg2);
    {
        dim3 grid(mTiles, HID_C / 128);
        gemm_mma<HID_C, HID_C, true ><<<grid, 256, SMEM>>>(
            (const float*)agg2, Wf3, b1b, (float*)t);
    }
    {
        dim3 grid(mTiles, OUT_C / 128);
        gemm_mma<HID_C, OUT_C, false><<<grid, 256, SMEM>>>(
            (const float*)t, Wf4, b2b, out);
    }
}

// round 8
// speedup vs baseline: 3.3390x; 1.0064x over previous
#include <cuda_runtime.h>
#include <cstdint>

#define N_NODES 100000
#define N_EDGES 1600000
#define IN_C 128
#define HID_C 256
#define OUT_C 128
#define SCAN_NB ((N_NODES + 1023) / 1024)   // 98

// ================= scratch (static device globals; no allocation) =================
__device__ float4 g_agg1[N_NODES * IN_C / 4];
__device__ float4 g_h   [N_NODES * HID_C / 4];
__device__ float4 g_agg2[N_NODES * HID_C / 4];
__device__ float  g_Wf1[IN_C * HID_C];       // fragment-packed weights
__device__ float  g_Wf2[HID_C * HID_C];
__device__ float  g_Wf3[HID_C * HID_C];
__device__ float  g_Wf4[HID_C * OUT_C];
__device__ int    g_cnt[N_NODES];
__device__ int    g_rowoff[N_NODES + 1];
__device__ int    g_cursor[N_NODES];
__device__ int    g_csrsrc[N_EDGES];
__device__ int    g_bsum[SCAN_NB];

// ================= helpers =================
__device__ __forceinline__ uint32_t smem_u32(const void* p) {
    uint32_t a;
    asm("{ .reg .u64 t; cvta.to.shared.u64 t, %1; cvt.u32.u64 %0, t; }" : "=r"(a) : "l"(p));
    return a;
}
__device__ __forceinline__ float round_tf32(float x) {
    float r;
    asm("cvt.rna.tf32.f32 %0, %1;" : "=f"(r) : "f"(x));
    return r;
}
__device__ __forceinline__ void cp_async16(uint32_t dst, const void* src, bool pred) {
    int sz = pred ? 16 : 0;
    asm volatile("cp.async.ca.shared.global [%0], [%1], 16, %2;"
                 :: "r"(dst), "l"(src), "r"(sz) : "memory");
}
#define CP_COMMIT() asm volatile("cp.async.commit_group;" ::: "memory")
#define CP_WAIT(n)  asm volatile("cp.async.wait_group %0;" :: "n"(n) : "memory")

__device__ __forceinline__ void mma_tf32(float* d, uint32_t a0, uint32_t a1,
                                         uint32_t a2, uint32_t a3,
                                         uint32_t b0, uint32_t b1) {
    asm volatile(
        "mma.sync.aligned.m16n8k8.row.col.f32.tf32.tf32.f32 "
        "{%0,%1,%2,%3}, {%4,%5,%6,%7}, {%8,%9}, {%0,%1,%2,%3};"
        : "+f"(d[0]), "+f"(d[1]), "+f"(d[2]), "+f"(d[3])
        : "r"(a0), "r"(a1), "r"(a2), "r"(a3), "r"(b0), "r"(b1));
}
__device__ __forceinline__ float4 f4add(float4 a, float4 b) {
    return make_float4(a.x + b.x, a.y + b.y, a.z + b.z, a.w + b.w);
}

// ================= weight fragment-pack =================
// Layout per 32-k group g: [ks(4)][wn(NT)][p(4)][lane(32)] float4s
// q = {W[k0][n0], W[k0+4][n0], W[k0][n1], W[k0+4][n1]},
// n0 = wn*64 + 2p*8 + lane/4, n1 = n0+8, k0 = g*32 + ks*8 + lane%4
template <int K, int NTOT>
__global__ void pack_kernel(const float* __restrict__ W, float* __restrict__ Wf)
{
    constexpr int NT = NTOT / 64;
    constexpr int PER_G = 512 * NT;             // float4s per g-block
    int id = blockIdx.x * 256 + threadIdx.x;
    if (id >= K * NTOT / 4) return;
    int q  = id % PER_G;
    int g  = id / PER_G;
    int lane = q & 31;
    int p    = (q >> 5) & 3;
    int wn   = (q >> 7) % NT;
    int ks   = (q >> 7) / NT;

    int n0 = wn * 64 + 2 * p * 8 + (lane >> 2);
    int k0 = g * 32 + ks * 8 + (lane & 3);
    float4 v;
    v.x = round_tf32(W[(size_t)k0       * NTOT + n0]);
    v.y = round_tf32(W[(size_t)(k0 + 4) * NTOT + n0]);
    v.z = round_tf32(W[(size_t)k0       * NTOT + n0 + 8]);
    v.w = round_tf32(W[(size_t)(k0 + 4) * NTOT + n0 + 8]);
    ((float4*)Wf)[id] = v;
}

// ================= CSR build =================
__global__ void hist_kernel(const int* __restrict__ dst, int* __restrict__ cnt)
{
    int e = blockIdx.x * 256 + threadIdx.x;
    if (e < N_EDGES) atomicAdd(&cnt[dst[e]], 1);
}

__global__ void scan1_kernel(const int* __restrict__ cnt, int* __restrict__ rowoff,
                             int* __restrict__ bsum)
{
    __shared__ int sh[1024];
    int tid = threadIdx.x;
    int i = blockIdx.x * 1024 + tid;
    int v = (i < N_NODES) ? cnt[i] : 0;
    sh[tid] = v;
    __syncthreads();
#pragma unroll
    for (int off = 1; off < 1024; off <<= 1) {
        int t = (tid >= off) ? sh[tid - off] : 0;
        __syncthreads();
        sh[tid] += t;
        __syncthreads();
    }
    if (i < N_NODES) rowoff[i] = sh[tid] - v;
    if (tid == 1023) bsum[blockIdx.x] = sh[tid];
}

__global__ void scan2_kernel(int* __restrict__ bsum)
{
    __shared__ int sh[128];
    int tid = threadIdx.x;
    int v = (tid < SCAN_NB) ? bsum[tid] : 0;
    sh[tid] = v;
    __syncthreads();
#pragma unroll
    for (int off = 1; off < 128; off <<= 1) {
        int t = (tid >= off) ? sh[tid - off] : 0;
        __syncthreads();
        sh[tid] += t;
        __syncthreads();
    }
    if (tid < SCAN_NB) bsum[tid] = sh[tid] - v;
}

__global__ void scan3_kernel(int* __restrict__ rowoff, const int* __restrict__ bsum,
                             int* __restrict__ cursor)
{
    int i = blockIdx.x * 1024 + threadIdx.x;
    if (i < N_NODES) {
        int r = rowoff[i] + bsum[blockIdx.x];
        rowoff[i] = r;
        cursor[i] = r;
    }
    if (i == 0) rowoff[N_NODES] = N_EDGES;
}

__global__ void fill_kernel(const int* __restrict__ src, const int* __restrict__ dst,
                            int* __restrict__ cursor, int* __restrict__ csrsrc)
{
    int e = blockIdx.x * 256 + threadIdx.x;
    if (e >= N_EDGES) return;
    int pos = atomicAdd(&cursor[dst[e]], 1);
    csrsrc[pos] = src[e];
}

// ================= CSR gather-reduce =================
template <int V>   // V = channels/4
__global__ void __launch_bounds__(256) csr_reduce_kernel(
    const float4* __restrict__ x,
    const int* __restrict__ rowoff,
    const int* __restrict__ csrsrc,
    float4* __restrict__ agg)
{
    constexpr int J = V / 32;
    int node = (int)((blockIdx.x * 256u + threadIdx.x) >> 5);
    if (node >= N_NODES) return;
    int lane = threadIdx.x & 31;

    float4 acc[J];
#pragma unroll
    for (int j = 0; j < J; j++)
        acc[j] = x[(size_t)node * V + j * 32 + lane];

    int b = __ldg(&rowoff[node]);
    int e = __ldg(&rowoff[node + 1]);
    for (; b + 1 < e; b += 2) {
        int s0 = __ldg(&csrsrc[b]);
        int s1 = __ldg(&csrsrc[b + 1]);
#pragma unroll
        for (int j = 0; j < J; j++) {
            float4 v0 = x[(size_t)s0 * V + j * 32 + lane];
            float4 v1 = x[(size_t)s1 * V + j * 32 + lane];
            acc[j] = f4add(acc[j], f4add(v0, v1));
        }
    }
    if (b < e) {
        int s0 = __ldg(&csrsrc[b]);
#pragma unroll
        for (int j = 0; j < J; j++)
            acc[j] = f4add(acc[j], x[(size_t)s0 * V + j * 32 + lane]);
    }
#pragma unroll
    for (int j = 0; j < J; j++)
        agg[(size_t)node * V + j * 32 + lane] = acc[j];
}

// ================= fused 2-layer MLP =================
// C[M,N2] = act( relu(A[M,K] @ W1[K,256] + b1) @ W2[256,N2] + b2 )
// BM=128, 512 threads = 16 warps (4m x 4n). Hidden tile kept in SMEM.
template <int K, int N2, bool OUTER_RELU>
__global__ void __launch_bounds__(512) fused_mlp(
    const float* __restrict__ A,
    const float* __restrict__ Wp1,    // packed [K x 256]
    const float* __restrict__ b1v,
    const float* __restrict__ Wp2,    // packed [256 x N2]
    const float* __restrict__ b2v,
    float* __restrict__ C)
{
    constexpr int BM = 128;
    constexpr int GA = K / 32, GB = HID_C / 32;
    constexpr int NT2 = N2 / 64;                  // 4 or 2
    constexpr int NF  = (N2 / 4) / 8;             // frags per warp n-dir: 8 or 4
    constexpr int NPL = NF / 2;                   // packed float4 loads per ks
    constexpr int M = N_NODES;
    constexpr int APITCH = 36, HPITCH = 260;
    constexpr int ABUF  = BM * APITCH;            // 4608 floats per buffer
    constexpr int W1OFF = 2 * ABUF;               // 9216
    constexpr int WBUF1 = 8192;                   // floats (2048 float4)
    constexpr int W2OFF = BM * HPITCH;            // 33280 (H region size)
    constexpr int WBUF2 = 512 * NT2 * 4;          // floats per buffer

    extern __shared__ float sm[];
    const uint32_t sbase = smem_u32(sm);

    const int tid  = threadIdx.x;
    const int wid  = tid >> 5;
    const int lane = tid & 31;
    const int gid  = lane >> 2;
    const int tig  = lane & 3;
    const int wm   = wid & 3;
    const int wn   = wid >> 2;                    // 0..3
    const int rA   = wm * 32;
    const int m0   = blockIdx.x * BM;

    float acc[2][8][4];
#pragma unroll
    for (int i = 0; i < 2; i++)
#pragma unroll
        for (int j = 0; j < 8; j++)
#pragma unroll
            for (int c = 0; c < 4; c++) acc[i][j][c] = 0.0f;

    // ---- phase A: H_acc = A @ W1 ----
    auto loadA = [&](int g) {
        const int s = g & 1;
#pragma unroll
        for (int j = 0; j < 2; j++) {             // A: 1024 float4
            int idx = j * 512 + tid;
            int row = idx >> 3, c4 = idx & 7;
            cp_async16(sbase + (uint32_t)(s * ABUF + row * APITCH + c4 * 4) * 4u,
                       A + (size_t)(m0 + row) * K + g * 32 + c4 * 4,
                       (m0 + row) < M);
        }
#pragma unroll
        for (int j = 0; j < 4; j++) {             // W1 chunk: 2048 float4
            int idx = j * 512 + tid;
            cp_async16(sbase + (uint32_t)(W1OFF + s * WBUF1 + idx * 4) * 4u,
                       Wp1 + ((size_t)g * 2048 + idx) * 4, true);
        }
        CP_COMMIT();
    };

    loadA(0);
    for (int g = 0; g < GA; g++) {
        if (g + 1 < GA) { loadA(g + 1); CP_WAIT(1); }
        else            { CP_WAIT(0); }
        __syncthreads();
        const float* as = sm + (g & 1) * ABUF;
        const float* bs = sm + W1OFF + (g & 1) * WBUF1;
#pragma unroll
        for (int ks = 0; ks < 4; ks++) {
            const int k0 = ks * 8;
            uint32_t a[2][4];
#pragma unroll
            for (int mf = 0; mf < 2; mf++) {
                int base = rA + mf * 16;
                a[mf][0] = __float_as_uint(round_tf32(as[(base + gid)     * APITCH + k0 + tig]));
                a[mf][1] = __float_as_uint(round_tf32(as[(base + gid + 8) * APITCH + k0 + tig]));
                a[mf][2] = __float_as_uint(round_tf32(as[(base + gid)     * APITCH + k0 + tig + 4]));
                a[mf][3] = __float_as_uint(round_tf32(as[(base + gid + 8) * APITCH + k0 + tig + 4]));
            }
            uint32_t b[8][2];
#pragma unroll
            for (int p = 0; p < 4; p++) {
                float4 q = *(const float4*)&bs[(((ks * 4 + wn) * 4 + p) * 32 + lane) * 4];
                b[2 * p][0]     = __float_as_uint(q.x);
                b[2 * p][1]     = __float_as_uint(q.y);
                b[2 * p + 1][0] = __float_as_uint(q.z);
                b[2 * p + 1][1] = __float_as_uint(q.w);
            }
#pragma unroll
            for (int mf = 0; mf < 2; mf++)
#pragma unroll
                for (int nf = 0; nf < 8; nf++)
                    mma_tf32(acc[mf][nf], a[mf][0], a[mf][1], a[mf][2], a[mf][3],
                             b[nf][0], b[nf][1]);
        }
        __syncthreads();
    }

    // ---- prefetch first W2 chunk ----
    auto loadB = [&](int g) {
        const int s = g & 1;
#pragma unroll
        for (int j = 0; j < NT2; j++) {
            int idx = j * 512 + tid;
            cp_async16(sbase + (uint32_t)(W2OFF + s * WBUF2 + idx * 4) * 4u,
                       Wp2 + ((size_t)g * 512 * NT2 + idx) * 4, true);
        }
        CP_COMMIT();
    };
    loadB(0);

    // ---- phase 3: spill H = round_tf32(relu(acc + b1)) to smem ----
    float* H = sm;
#pragma unroll
    for (int nf = 0; nf < 8; nf++) {
        int col = wn * 64 + nf * 8 + tig * 2;
        float c0 = b1v[col], c1 = b1v[col + 1];
#pragma unroll
        for (int mf = 0; mf < 2; mf++) {
            int r0 = rA + mf * 16 + gid;
            H[(size_t)r0 * HPITCH + col]           = round_tf32(fmaxf(acc[mf][nf][0] + c0, 0.f));
            H[(size_t)r0 * HPITCH + col + 1]       = round_tf32(fmaxf(acc[mf][nf][1] + c1, 0.f));
            H[(size_t)(r0 + 8) * HPITCH + col]     = round_tf32(fmaxf(acc[mf][nf][2] + c0, 0.f));
            H[(size_t)(r0 + 8) * HPITCH + col + 1] = round_tf32(fmaxf(acc[mf][nf][3] + c1, 0.f));
        }
    }
    // reset accumulators for phase 4
#pragma unroll
    for (int i = 0; i < 2; i++)
#pragma unroll
        for (int j = 0; j < 8; j++)
#pragma unroll
            for (int c = 0; c < 4; c++) acc[i][j][c] = 0.0f;

    // ---- phase 4: OUT = H @ W2 ----
    const int grp = (NF == 8) ? wn : (wn >> 1);
    for (int g = 0; g < GB; g++) {
        if (g + 1 < GB) { loadB(g + 1); CP_WAIT(1); }
        else            { CP_WAIT(0); }
        __syncthreads();           // g==0: also orders H writes before reads
        const float* bs = sm + W2OFF + (g & 1) * WBUF2;
#pragma unroll
        for (int ks = 0; ks < 4; ks++) {
            const int k0 = g * 32 + ks * 8;
            uint32_t a[2][4];
#pragma unroll
            for (int mf = 0; mf < 2; mf++) {
                int base = rA + mf * 16;
                a[mf][0] = __float_as_uint(H[(size_t)(base + gid)     * HPITCH + k0 + tig]);
                a[mf][1] = __float_as_uint(H[(size_t)(base + gid + 8) * HPITCH + k0 + tig]);
                a[mf][2] = __float_as_uint(H[(size_t)(base + gid)     * HPITCH + k0 + tig + 4]);
                a[mf][3] = __float_as_uint(H[(size_t)(base + gid + 8) * HPITCH + k0 + tig + 4]);
            }
            uint32_t b[8][2];
#pragma unroll
            for (int pl = 0; pl < NPL; pl++) {
                int p = (NF == 8) ? pl : (2 * (wn & 1) + pl);
                float4 q = *(const float4*)&bs[(((ks * NT2 + grp) * 4 + p) * 32 + lane) * 4];
                b[2 * pl][0]     = __float_as_uint(q.x);
                b[2 * pl][1]     = __float_as_uint(q.y);
                b[2 * pl + 1][0] = __float_as_uint(q.z);
                b[2 * pl + 1][1] = __float_as_uint(q.w);
            }
#pragma unroll
            for (int mf = 0; mf < 2; mf++)
#pragma unroll
                for (int nf = 0; nf < NF; nf++)
                    mma_tf32(acc[mf][nf], a[mf][0], a[mf][1], a[mf][2], a[mf][3],
                             b[nf][0], b[nf][1]);
        }
        __syncthreads();
    }

    // ---- epilogue ----
#pragma unroll
    for (int nf = 0; nf < NF; nf++) {
        int col = wn * (N2 / 4) + nf * 8 + tig * 2;
        float c0 = b2v[col], c1 = b2v[col + 1];
#pragma unroll
        for (int mf = 0; mf < 2; mf++) {
            int r0 = m0 + rA + mf * 16 + gid;
            float v0 = acc[mf][nf][0] + c0, v1 = acc[mf][nf][1] + c1;
            float v2 = acc[mf][nf][2] + c0, v3 = acc[mf][nf][3] + c1;
            if (OUTER_RELU) {
                v0 = fmaxf(v0, 0.f); v1 = fmaxf(v1, 0.f);
                v2 = fmaxf(v2, 0.f); v3 = fmaxf(v3, 0.f);
            }
            if (r0 < M)     *(float2*)&C[(size_t)r0 * N2 + col]       = make_float2(v0, v1);
            if (r0 + 8 < M) *(float2*)&C[(size_t)(r0 + 8) * N2 + col] = make_float2(v2, v3);
        }
    }
}

// ================= launch =================
extern "C" void kernel_launch(void* const* d_in, const int* in_sizes, int n_in,
                              void* d_out, int out_size)
{
    const float* x   = (const float*)d_in[0];
    const int*   ei  = (const int*)d_in[1];
    const float* W1a = (const float*)d_in[2];
    const float* b1a = (const float*)d_in[3];
    const float* W2a = (const float*)d_in[4];
    const float* b2a = (const float*)d_in[5];
    const float* W1b = (const float*)d_in[6];
    const float* b1b = (const float*)d_in[7];
    const float* W2b = (const float*)d_in[8];
    const float* b2b = (const float*)d_in[9];
    float* out = (float*)d_out;

    float4 *agg1, *h, *agg2;
    float *Wf1, *Wf2, *Wf3, *Wf4;
    int *cnt, *rowoff, *cursor, *csrsrc, *bsum;
    cudaGetSymbolAddress((void**)&agg1, g_agg1);
    cudaGetSymbolAddress((void**)&h,    g_h);
    cudaGetSymbolAddress((void**)&agg2, g_agg2);
    cudaGetSymbolAddress((void**)&Wf1,  g_Wf1);
    cudaGetSymbolAddress((void**)&Wf2,  g_Wf2);
    cudaGetSymbolAddress((void**)&Wf3,  g_Wf3);
    cudaGetSymbolAddress((void**)&Wf4,  g_Wf4);
    cudaGetSymbolAddress((void**)&cnt,    g_cnt);
    cudaGetSymbolAddress((void**)&rowoff, g_rowoff);
    cudaGetSymbolAddress((void**)&cursor, g_cursor);
    cudaGetSymbolAddress((void**)&csrsrc, g_csrsrc);
    cudaGetSymbolAddress((void**)&bsum,   g_bsum);

    const int* src = ei;
    const int* dst = ei + N_EDGES;

    const int mTiles = (N_NODES + 127) / 128;   // 782
    const int eBlocks = (N_EDGES + 255) / 256;
    const int nWarpBlocks = (N_NODES * 32 + 255) / 256;

    // fused MLP smem: H(133120B) + 2x W2 chunk
    const int SM1 = (128 * 260 + 2 * 512 * 4 * 4) * 4;   // N2=256: 198656
    const int SM2 = (128 * 260 + 2 * 512 * 2 * 4) * 4;   // N2=128: 165888
    cudaFuncSetAttribute(fused_mlp<IN_C,  HID_C, true >,
                         cudaFuncAttributeMaxDynamicSharedMemorySize, SM1);
    cudaFuncSetAttribute(fused_mlp<HID_C, OUT_C, false>,
                         cudaFuncAttributeMaxDynamicSharedMemorySize, SM2);

    // ---- CSR build (dst-sorted) ----
    cudaMemsetAsync(cnt, 0, N_NODES * sizeof(int));
    hist_kernel<<<eBlocks, 256>>>(dst, cnt);
    scan1_kernel<<<SCAN_NB, 1024>>>(cnt, rowoff, bsum);
    scan2_kernel<<<1, 128>>>(bsum);
    scan3_kernel<<<SCAN_NB, 1024>>>(rowoff, bsum, cursor);
    fill_kernel<<<eBlocks, 256>>>(src, dst, cursor, csrsrc);

    // ---- weight fragment packs (tiny) ----
    pack_kernel<IN_C,  HID_C><<<(IN_C * HID_C / 4 + 255) / 256, 256>>>(W1a, Wf1);
    pack_kernel<HID_C, HID_C><<<(HID_C * HID_C / 4 + 255) / 256, 256>>>(W2a, Wf2);
    pack_kernel<HID_C, HID_C><<<(HID_C * HID_C / 4 + 255) / 256, 256>>>(W1b, Wf3);
    pack_kernel<HID_C, OUT_C><<<(HID_C * OUT_C / 4 + 255) / 256, 256>>>(W2b, Wf4);

    // ---- conv1: reduce + fused MLP (outer relu) ----
    csr_reduce_kernel<IN_C / 4><<<nWarpBlocks, 256>>>(
        (const float4*)x, rowoff, csrsrc, agg1);
    fused_mlp<IN_C, HID_C, true><<<mTiles, 512, SM1>>>(
        (const float*)agg1, Wf1, b1a, Wf2, b2a, (float*)h);

    // ---- conv2: reduce + fused MLP (no outer relu) ----
    csr_reduce_kernel<HID_C / 4><<<nWarpBlocks, 256>>>(
        (const float4*)h, rowoff, csrsrc, agg2);
    fused_mlp<HID_C, OUT_C, false><<<mTiles, 512, SM2>>>(
        (const float*)agg2, Wf3, b1b, Wf4, b2b, out);
}